// round 1
// baseline (speedup 1.0000x reference)
#include <cuda_runtime.h>
#include <cstdint>

typedef unsigned long long ull;

// Scratch: transposed + duplicated embedding, and 0.5*||e||^2 per code.
//   g_Et2[k][2*c] = g_Et2[k][2*c+1] = E[c][k]   (k = channel 0..127, c = code 0..511)
__device__ __align__(16) float g_Et2[128 * 1024];
__device__ float g_hhalf[512];

__global__ void vq_prep_kernel(const float* __restrict__ emb) {
    int t = blockIdx.x * blockDim.x + threadIdx.x;
    int nt = gridDim.x * blockDim.x;
    for (int i = t; i < 512 * 128; i += nt) {
        int code = i >> 7, k = i & 127;
        float v = emb[i];
        g_Et2[k * 1024 + 2 * code]     = v;
        g_Et2[k * 1024 + 2 * code + 1] = v;
    }
    if (t < 512) {
        const float* row = emb + t * 128;
        float s = 0.f;
        #pragma unroll 4
        for (int c = 0; c < 128; ++c) { float v = row[c]; s += v * v; }
        g_hhalf[t] = 0.5f * s;
    }
}

__device__ __forceinline__ void ffma2(ull& d, ull a, ull b) {
    asm("fma.rn.f32x2 %0, %1, %2, %0;" : "+l"(d) : "l"(a), "l"(b));
}
__device__ __forceinline__ float lo32(ull v) { return __uint_as_float((unsigned)v); }
__device__ __forceinline__ float hi32(ull v) { return __uint_as_float((unsigned)(v >> 32)); }
// monotonic float -> uint mapping (handles negatives), for packed-min argmin
__device__ __forceinline__ unsigned fkey(float f) {
    unsigned u = __float_as_uint(f);
    return (u & 0x80000000u) ? ~u : (u | 0x80000000u);
}

// SMEM layout (floats): Zs[128][132] | Es[32][256] | bestS[128] (as ull)
#define ZS_STRIDE 132
#define ZS_FLOATS (128 * ZS_STRIDE)
#define ES_FLOATS (32 * 256)
#define SMEM_BYTES ((ZS_FLOATS + ES_FLOATS) * 4 + 128 * 8)

__global__ __launch_bounds__(256, 2)
void vq_main_kernel(const float* __restrict__ z, const float* __restrict__ emb,
                    float* __restrict__ out) {
    extern __shared__ float sm[];
    float* Zs = sm;                            // 128 rows (k) x 132 (128 px + pad)
    float* Es = sm + ZS_FLOATS;                // 32 rows (k) x 256 (128 codes duplicated)
    ull*   bestS = (ull*)(sm + ZS_FLOATS + ES_FLOATS);

    const int tid = threadIdx.x;
    const int tx = tid & 15;   // pixel group
    const int ty = tid >> 4;   // code group
    const int b  = blockIdx.x >> 5;
    const int p0 = (blockIdx.x & 31) << 7;

    const float* zsrc = z + (size_t)b * 128 * 4096 + p0;

    // Load Z tile: 128 channels x 128 pixels (rows contiguous in gmem -> coalesced)
    #pragma unroll
    for (int i = 0; i < 16; ++i) {
        int f = tid + i * 256;            // float4 id, 4096 total
        int r = f >> 5, c4 = (f & 31) << 2;
        *(float4*)(Zs + r * ZS_STRIDE + c4) =
            *(const float4*)(zsrc + (size_t)r * 4096 + c4);
    }
    if (tid < 128) bestS[tid] = 0xFFFFFFFFFFFFFFFFull;
    // first __syncthreads below covers both the Z tile and bestS init

    for (int cc = 0; cc < 4; ++cc) {           // code chunks of 128
        ull acc[4][8];
        #pragma unroll
        for (int p = 0; p < 4; ++p)
            #pragma unroll
            for (int j = 0; j < 8; ++j) acc[p][j] = 0ull;

        for (int kt = 0; kt < 4; ++kt) {       // k tiles of 32
            __syncthreads();
            const float* src = g_Et2 + (size_t)(kt * 32) * 1024 + cc * 256;
            #pragma unroll
            for (int i = 0; i < 8; ++i) {
                int f = tid + i * 256;         // float4 id, 2048 total
                int r = f >> 6, c4 = (f & 63) << 2;
                *(float4*)(Es + r * 256 + c4) = *(const float4*)(src + (size_t)r * 1024 + c4);
            }
            __syncthreads();

            #pragma unroll 4
            for (int kk = 0; kk < 32; ++kk) {
                const float* zr = Zs + (kt * 32 + kk) * ZS_STRIDE;
                const float* er = Es + kk * 256;
                ulonglong2 za = *(const ulonglong2*)(zr + 4 * tx);        // px 4tx..4tx+3
                ulonglong2 zb = *(const ulonglong2*)(zr + 64 + 4 * tx);   // px 64+4tx..
                ulonglong2 e0 = *(const ulonglong2*)(er + 8 * ty);        // codes 4ty,4ty+1 (dup)
                ulonglong2 e1 = *(const ulonglong2*)(er + 8 * ty + 4);    // codes 4ty+2,4ty+3
                ulonglong2 e2 = *(const ulonglong2*)(er + 128 + 8 * ty);  // codes 64+4ty,..
                ulonglong2 e3 = *(const ulonglong2*)(er + 128 + 8 * ty + 4);
                ull zp0 = za.x, zp1 = za.y, zp2 = zb.x, zp3 = zb.y;
                ull ep[8] = {e0.x, e0.y, e1.x, e1.y, e2.x, e2.y, e3.x, e3.y};
                #pragma unroll
                for (int j = 0; j < 8; ++j) {
                    ffma2(acc[0][j], zp0, ep[j]);
                    ffma2(acc[1][j], zp1, ep[j]);
                    ffma2(acc[2][j], zp2, ep[j]);
                    ffma2(acc[3][j], zp3, ep[j]);
                }
            }
        }

        // per-chunk argmin update (dist surrogate = 0.5*||e||^2 - z.e)
        int codeid[8];
        float hh[8];
        #pragma unroll
        for (int j = 0; j < 8; ++j) {
            int local = (j < 4) ? (4 * ty + j) : (64 + 4 * ty + (j - 4));
            codeid[j] = (cc << 7) + local;
            hh[j] = g_hhalf[codeid[j]];
        }
        #pragma unroll
        for (int p = 0; p < 4; ++p) {
            int pxbase = ((p < 2) ? 0 : 64) + 4 * tx + ((p & 1) << 1);
            {
                float bd = 3.4e38f; int bi = 0;
                #pragma unroll
                for (int j = 0; j < 8; ++j) {          // codes ascend -> strict < keeps first
                    float d = hh[j] - lo32(acc[p][j]);
                    if (d < bd) { bd = d; bi = codeid[j]; }
                }
                atomicMin(&bestS[pxbase], ((ull)fkey(bd) << 32) | (unsigned)bi);
            }
            {
                float bd = 3.4e38f; int bi = 0;
                #pragma unroll
                for (int j = 0; j < 8; ++j) {
                    float d = hh[j] - hi32(acc[p][j]);
                    if (d < bd) { bd = d; bi = codeid[j]; }
                }
                atomicMin(&bestS[pxbase + 1], ((ull)fkey(bd) << 32) | (unsigned)bi);
            }
        }
    }

    __syncthreads();   // all atomics done; Zs free for reuse as gather stage

    // Gather winning embeddings into Zs as Qs[c][px] (coalesced E reads)
    {
        int px = tid >> 1, half = tid & 1;
        unsigned idx = (unsigned)bestS[px];
        const float* er = emb + (size_t)idx * 128 + 64 * half;
        #pragma unroll
        for (int i = 0; i < 16; ++i) {
            float4 v = *(const float4*)(er + 4 * i);
            int c = 64 * half + 4 * i;
            Zs[(c + 0) * ZS_STRIDE + px] = v.x;
            Zs[(c + 1) * ZS_STRIDE + px] = v.y;
            Zs[(c + 2) * ZS_STRIDE + px] = v.z;
            Zs[(c + 3) * ZS_STRIDE + px] = v.w;
        }
    }
    __syncthreads();

    // Coalesced output write: out[b, c, p0 + 0..127]
    {
        int r = tid >> 1, half = tid & 1;
        float* orow = out + (size_t)b * 128 * 4096 + (size_t)r * 4096 + p0 + 64 * half;
        const float* q = Zs + r * ZS_STRIDE + 64 * half;
        #pragma unroll
        for (int i = 0; i < 16; ++i)
            *(float4*)(orow + 4 * i) = *(const float4*)(q + 4 * i);
    }
}

extern "C" void kernel_launch(void* const* d_in, const int* in_sizes, int n_in,
                              void* d_out, int out_size) {
    const float* z   = (const float*)d_in[0];   // (32,128,64,64) fp32
    const float* emb = (const float*)d_in[1];   // (512,128) fp32
    float* out = (float*)d_out;                 // (32,128,64,64) fp32

    cudaFuncSetAttribute(vq_main_kernel,
                         cudaFuncAttributeMaxDynamicSharedMemorySize, SMEM_BYTES);

    vq_prep_kernel<<<64, 256>>>(emb);
    vq_main_kernel<<<1024, 256, SMEM_BYTES>>>(z, emb, out);
}

// round 3
// speedup vs baseline: 1.0879x; 1.0879x over previous
#include <cuda_runtime.h>
#include <cstdint>

typedef unsigned long long ull;
typedef unsigned int u32;

// ---------------- global scratch (static, no allocs) ----------------
// E fragment image: [h(2)][ce(4)][hl(2)][tl(4)][nblk(32)][64 floats] = 512KB
__device__ __align__(16) float g_Eimg[131072];
__device__ float g_hhalf[512];   // 0.5*||e_k||^2

__device__ __forceinline__ void tf32split(float v, float& hi, float& lo) {
    u32 uh; asm("cvt.rna.tf32.f32 %0, %1;" : "=r"(uh) : "f"(v));
    hi = __uint_as_float(uh);
    float r = v - hi;
    u32 ul; asm("cvt.rna.tf32.f32 %0, %1;" : "=r"(ul) : "f"(r));
    lo = __uint_as_float(ul);
}
__device__ __forceinline__ unsigned fkey(float f) {   // monotonic float->uint
    unsigned u = __float_as_uint(f);
    return (u & 0x80000000u) ? ~u : (u | 0x80000000u);
}
__device__ __forceinline__ void mma8(float* c, float2 a02, float2 a13, float2 b) {
    asm("mma.sync.aligned.m16n8k8.row.col.f32.tf32.tf32.f32 "
        "{%0,%1,%2,%3}, {%4,%5,%6,%7}, {%8,%9}, {%0,%1,%2,%3};"
        : "+f"(c[0]), "+f"(c[1]), "+f"(c[2]), "+f"(c[3])
        : "r"(__float_as_uint(a02.x)), "r"(__float_as_uint(a13.x)),
          "r"(__float_as_uint(a02.y)), "r"(__float_as_uint(a13.y)),
          "r"(__float_as_uint(b.x)),  "r"(__float_as_uint(b.y)));
}

// ---------------- prep: build E fragment image + half-norms ----------------
__global__ void vq_prep(const float* __restrict__ emb) {
    int t = blockIdx.x * blockDim.x + threadIdx.x;
    int nt = gridDim.x * blockDim.x;
    for (int i = t; i < 512 * 128; i += nt) {
        int code = i >> 7, k = i & 127;
        int h = code >> 8, nblk = (code >> 3) & 31, colg = code & 7;
        int ce = k >> 5, tl = (k >> 3) & 3, j = k & 3, c = (k >> 2) & 1;
        int slot = 2 * (4 * colg + j) + c;
        float hi, lo;
        tf32split(emb[i], hi, lo);
        int base = (((h * 4 + ce) * 2 + 0) * 4 + tl) * 2048 + nblk * 64 + slot;
        g_Eimg[base] = hi;              // hl=0 plane
        g_Eimg[base + 8192] = lo;       // hl=1 plane (+4*2048)
    }
    if (t < 512) {
        const float* row = emb + t * 128;
        float s = 0.f;
        #pragma unroll 4
        for (int c = 0; c < 128; ++c) { float v = row[c]; s += v * v; }
        g_hhalf[t] = 0.5f * s;
    }
}

// ---------------- main kernel ----------------
// SMEM float offsets:
//  Z planes [(ahl*2+kh)]: 4 x 9216   -> 0 .. 36864     (px stride 72)
//  E chunk  [hl][tl][nblk][64]       -> 36864 .. 53248
//  hh[512]                           -> 53248
//  bestS[128] (ull)                  -> float idx 53760
#define ZOFF   0
#define EOFF   36864
#define HHOFF  53248
#define BESTF  53760
#define SMEM_BYTES ((BESTF + 256) * 4)
#define QS_STRIDE 132

__global__ __launch_bounds__(256, 1)
void vq_mma_kernel(const float* __restrict__ z, const float* __restrict__ emb,
                   float* __restrict__ out) {
    extern __shared__ float SMF[];
    float* hh_s = SMF + HHOFF;
    ull* bestS = (ull*)(SMF + BESTF);

    const int tid = threadIdx.x;
    const int wid = tid >> 5, lane = tid & 31;
    const int jj = lane & 3, q = lane >> 2;
    const int pg = wid & 3, cg = wid >> 2;
    const int px0 = pg << 5;
    const int b = blockIdx.x >> 5;
    const int p0 = (blockIdx.x & 31) << 7;

    const float* zb = z + (size_t)b * 128 * 4096 + p0;

    hh_s[tid] = g_hhalf[tid];
    hh_s[tid + 256] = g_hhalf[tid + 256];
    if (tid < 128) bestS[tid] = ~0ull;

    // ---- Z producer: split z tile into tf32 hi/lo fragment planes ----
    {
        int px = tid & 127, kh = tid >> 7;          // kh: k 0..63 / 64..127
        const float* zc = zb + px + (size_t)kh * 64 * 4096;
        float* Zh = SMF + ZOFF + (0 * 2 + kh) * 9216 + px * 72;
        float* Zl = SMF + ZOFF + (1 * 2 + kh) * 9216 + px * 72;
        int swz = 2 * ((px >> 2) & 3);
        #pragma unroll
        for (int T = 0; T < 8; ++T) {
            #pragma unroll
            for (int j = 0; j < 4; ++j) {
                float v0 = zc[(size_t)(8 * T + j) * 4096];
                float v1 = zc[(size_t)(8 * T + j + 4) * 4096];
                float h0, l0, h1, l1;
                tf32split(v0, h0, l0);
                tf32split(v1, h1, l1);
                int kp = (8 * T + 2 * j) ^ swz;
                *(float2*)(Zh + kp) = make_float2(h0, h1);
                *(float2*)(Zl + kp) = make_float2(l0, l1);
            }
        }
    }

    const int s0 = 2 * (q >> 2);      // A-frag swizzle, rows q / q+16
    const int s1 = s0 + 4;            // rows q+8 / q+24

    for (int h = 0; h < 2; ++h) {
        float acc[2][16][4];
        #pragma unroll
        for (int m = 0; m < 2; ++m)
            #pragma unroll
            for (int n = 0; n < 16; ++n)
                #pragma unroll
                for (int r = 0; r < 4; ++r) acc[m][n][r] = 0.f;

        for (int ce = 0; ce < 4; ++ce) {
            __syncthreads();
            {   // copy E chunk (64KB): identity float4 copy
                const float4* src = (const float4*)(g_Eimg + (h * 4 + ce) * 16384);
                float4* dst = (float4*)(SMF + EOFF);
                #pragma unroll
                for (int i = 0; i < 16; ++i)
                    dst[tid + i * 256] = src[tid + i * 256];
            }
            __syncthreads();

            #pragma unroll
            for (int pass = 0; pass < 3; ++pass) {
                const float* Zbase = SMF + ZOFF + ((pass == 2) ? 2 : 0) * 9216;
                const float* Eb0 = SMF + EOFF + ((pass == 1) ? 8192 : 0) + cg * 1024 + 2 * lane;
                #pragma unroll
                for (int tl = 0; tl < 4; ++tl) {
                    int t = ce * 4 + tl;
                    const float* Zp = Zbase + (t >> 3) * 9216;
                    int koff = 8 * (t & 7) + 2 * jj;
                    float2 A00 = *(const float2*)(Zp + (px0 + q) * 72      + (koff ^ s0));
                    float2 A01 = *(const float2*)(Zp + (px0 + q + 8) * 72  + (koff ^ s1));
                    float2 A10 = *(const float2*)(Zp + (px0 + q + 16) * 72 + (koff ^ s0));
                    float2 A11 = *(const float2*)(Zp + (px0 + q + 24) * 72 + (koff ^ s1));
                    const float* Eb = Eb0 + tl * 2048;
                    #pragma unroll
                    for (int n = 0; n < 16; ++n) {
                        float2 B = *(const float2*)(Eb + n * 64);
                        mma8(acc[0][n], A00, A01, B);
                        mma8(acc[1][n], A10, A11, B);
                    }
                }
            }
        }

        // ---- per-half argmin: dist = 0.5||e||^2 - z.e ----
        #pragma unroll
        for (int m = 0; m < 2; ++m) {
            ull bA = ~0ull, bB = ~0ull;
            #pragma unroll
            for (int n = 0; n < 16; ++n) {
                int c = h * 256 + cg * 128 + 8 * n + 2 * jj;
                float hc0 = hh_s[c], hc1 = hh_s[c + 1];
                ull kA0 = ((ull)fkey(hc0 - acc[m][n][0]) << 32) | (u32)c;
                ull kA1 = ((ull)fkey(hc1 - acc[m][n][1]) << 32) | (u32)(c + 1);
                ull kB0 = ((ull)fkey(hc0 - acc[m][n][2]) << 32) | (u32)c;
                ull kB1 = ((ull)fkey(hc1 - acc[m][n][3]) << 32) | (u32)(c + 1);
                ull a = kA0 < kA1 ? kA0 : kA1;
                ull bb = kB0 < kB1 ? kB0 : kB1;
                if (a < bA) bA = a;
                if (bb < bB) bB = bb;
            }
            #pragma unroll
            for (int d = 1; d <= 2; d <<= 1) {
                ull oa = __shfl_xor_sync(0xffffffffu, bA, d);
                ull ob = __shfl_xor_sync(0xffffffffu, bB, d);
                if (oa < bA) bA = oa;
                if (ob < bB) bB = ob;
            }
            if (jj == 0) {
                atomicMin(&bestS[px0 + 16 * m + q], bA);
                atomicMin(&bestS[px0 + 16 * m + q + 8], bB);
            }
        }
    }

    __syncthreads();   // bestS final; Z planes reusable as gather staging

    // ---- gather winning rows into Qs[c][px], then coalesced write ----
    {
        int px = tid >> 1, half = tid & 1;
        u32 idx = (u32)bestS[px];
        const float* er = emb + (size_t)idx * 128 + 64 * half;
        float* Qs = SMF + ZOFF;
        #pragma unroll
        for (int i = 0; i < 16; ++i) {
            float4 v = *(const float4*)(er + 4 * i);
            int c = 64 * half + 4 * i;
            Qs[(c + 0) * QS_STRIDE + px] = v.x;
            Qs[(c + 1) * QS_STRIDE + px] = v.y;
            Qs[(c + 2) * QS_STRIDE + px] = v.z;
            Qs[(c + 3) * QS_STRIDE + px] = v.w;
        }
    }
    __syncthreads();
    {
        int r = tid >> 1, half = tid & 1;
        float* orow = out + (size_t)b * 128 * 4096 + (size_t)r * 4096 + p0 + 64 * half;
        const float* qrow = SMF + ZOFF + r * QS_STRIDE + 64 * half;
        #pragma unroll
        for (int i = 0; i < 16; ++i)
            *(float4*)(orow + 4 * i) = *(const float4*)(qrow + 4 * i);
    }
}

extern "C" void kernel_launch(void* const* d_in, const int* in_sizes, int n_in,
                              void* d_out, int out_size) {
    const float* z   = (const float*)d_in[0];   // (32,128,64,64) fp32
    const float* emb = (const float*)d_in[1];   // (512,128) fp32
    float* out = (float*)d_out;

    cudaFuncSetAttribute(vq_mma_kernel,
                         cudaFuncAttributeMaxDynamicSharedMemorySize, SMEM_BYTES);

    vq_prep<<<64, 256>>>(emb);
    vq_mma_kernel<<<1024, 256, SMEM_BYTES>>>(z, emb, out);
}

// round 4
// speedup vs baseline: 1.3065x; 1.2010x over previous
#include <cuda_runtime.h>
#include <cstdint>

typedef unsigned long long ull;
typedef unsigned int u32;

// ---------------- global scratch (static, no allocs) ----------------
// E fragment image: [h(2)][ce(4)][hl(2)][tl(4)][nblk(32)][64 floats] = 512KB
// sub-chunk c = h*8+ce*2+hl  ->  contiguous 8192 floats (32KB)
__device__ __align__(16) float g_Eimg[131072];
__device__ float g_hhalf[512];   // 0.5*||e_k||^2

__device__ __forceinline__ void tf32split(float v, float& hi, float& lo) {
    u32 uh; asm("cvt.rna.tf32.f32 %0, %1;" : "=r"(uh) : "f"(v));
    hi = __uint_as_float(uh);
    float r = v - hi;
    u32 ul; asm("cvt.rna.tf32.f32 %0, %1;" : "=r"(ul) : "f"(r));
    lo = __uint_as_float(ul);
}
__device__ __forceinline__ unsigned fkey(float f) {   // monotonic float->uint
    unsigned u = __float_as_uint(f);
    return (u & 0x80000000u) ? ~u : (u | 0x80000000u);
}
__device__ __forceinline__ void mma8(float* c, float2 a02, float2 a13, float2 b) {
    asm("mma.sync.aligned.m16n8k8.row.col.f32.tf32.tf32.f32 "
        "{%0,%1,%2,%3}, {%4,%5,%6,%7}, {%8,%9}, {%0,%1,%2,%3};"
        : "+f"(c[0]), "+f"(c[1]), "+f"(c[2]), "+f"(c[3])
        : "r"(__float_as_uint(a02.x)), "r"(__float_as_uint(a13.x)),
          "r"(__float_as_uint(a02.y)), "r"(__float_as_uint(a13.y)),
          "r"(__float_as_uint(b.x)),  "r"(__float_as_uint(b.y)));
}
__device__ __forceinline__ u32 smem_u32(const void* p) {
    u32 a;
    asm("{ .reg .u64 t; cvta.to.shared.u64 t, %1; cvt.u32.u64 %0, t; }" : "=r"(a) : "l"(p));
    return a;
}
__device__ __forceinline__ void cp16(u32 dst, const void* src) {
    asm volatile("cp.async.cg.shared.global [%0], [%1], 16;" :: "r"(dst), "l"(src));
}
#define CP_COMMIT() asm volatile("cp.async.commit_group;" ::: "memory")
#define CP_WAIT1()  asm volatile("cp.async.wait_group 1;" ::: "memory")
#define CP_WAIT0()  asm volatile("cp.async.wait_group 0;" ::: "memory")

// ---------------- prep: build E fragment image + half-norms ----------------
__global__ void vq_prep(const float* __restrict__ emb) {
    int t = blockIdx.x * blockDim.x + threadIdx.x;
    int nt = gridDim.x * blockDim.x;
    for (int i = t; i < 512 * 128; i += nt) {
        int code = i >> 7, k = i & 127;
        int h = code >> 8, nblk = (code >> 3) & 31, colg = code & 7;
        int ce = k >> 5, tl = (k >> 3) & 3, j = k & 3, c = (k >> 2) & 1;
        int slot = 2 * (4 * colg + j) + c;
        float hi, lo;
        tf32split(emb[i], hi, lo);
        int base = (((h * 4 + ce) * 2 + 0) * 4 + tl) * 2048 + nblk * 64 + slot;
        g_Eimg[base] = hi;              // hl=0 plane
        g_Eimg[base + 8192] = lo;       // hl=1 plane
    }
    if (t < 512) {
        const float* row = emb + t * 128;
        float s = 0.f;
        #pragma unroll 4
        for (int c = 0; c < 128; ++c) { float v = row[c]; s += v * v; }
        g_hhalf[t] = 0.5f * s;
    }
}

// ---------------- main kernel ----------------
// SMEM float offsets:
//  Z planes [(ahl*2+kh)]: 4 x 9216   -> 0 .. 36864  (px stride 72)
//  E buffers: 2 x 8192               -> 36864 .. 53248
//  hh[512]                           -> 53248
//  bestS[128] (ull)                  -> float idx 53760
#define EOFF   36864
#define HHOFF  53248
#define BESTF  53760
#define SMEM_BYTES ((BESTF + 256) * 4)
#define QS_STRIDE 132

__device__ __forceinline__ void mma_block(
    const float* __restrict__ SMF, const float* __restrict__ ebuf,
    int ce, int px0, int cg, int q, int lane, int jj, int s0, int s1,
    bool twoPass, float acc[2][8][4])
{
    #pragma unroll
    for (int tl = 0; tl < 4; ++tl) {
        int t = ce * 4 + tl;
        const float* Zh = SMF + (t >> 3) * 9216;
        const float* Zl = SMF + (2 + (t >> 3)) * 9216;
        int koff = 8 * (t & 7) + 2 * jj;
        const float* Eb = ebuf + tl * 2048 + cg * 512 + 2 * lane;
        float2 Bf[8];
        #pragma unroll
        for (int n = 0; n < 8; ++n) Bf[n] = *(const float2*)(Eb + n * 64);
        float2 A00 = *(const float2*)(Zh + (px0 + q) * 72      + (koff ^ s0));
        float2 A01 = *(const float2*)(Zh + (px0 + q + 8) * 72  + (koff ^ s1));
        float2 A10 = *(const float2*)(Zh + (px0 + q + 16) * 72 + (koff ^ s0));
        float2 A11 = *(const float2*)(Zh + (px0 + q + 24) * 72 + (koff ^ s1));
        #pragma unroll
        for (int n = 0; n < 8; ++n) {
            mma8(acc[0][n], A00, A01, Bf[n]);
            mma8(acc[1][n], A10, A11, Bf[n]);
        }
        if (twoPass) {   // A-lo pass reusing the same B fragments (Bh chunk)
            A00 = *(const float2*)(Zl + (px0 + q) * 72      + (koff ^ s0));
            A01 = *(const float2*)(Zl + (px0 + q + 8) * 72  + (koff ^ s1));
            A10 = *(const float2*)(Zl + (px0 + q + 16) * 72 + (koff ^ s0));
            A11 = *(const float2*)(Zl + (px0 + q + 24) * 72 + (koff ^ s1));
            #pragma unroll
            for (int n = 0; n < 8; ++n) {
                mma8(acc[0][n], A00, A01, Bf[n]);
                mma8(acc[1][n], A10, A11, Bf[n]);
            }
        }
    }
}

__global__ __launch_bounds__(512, 1)
void vq_mma_kernel(const float* __restrict__ z, const float* __restrict__ emb,
                   float* __restrict__ out) {
    extern __shared__ float SMF[];
    float* hh_s = SMF + HHOFF;
    ull* bestS = (ull*)(SMF + BESTF);

    const int tid = threadIdx.x;
    const int wid = tid >> 5, lane = tid & 31;
    const int jj = lane & 3, q = lane >> 2;
    const int pg = wid & 3, cg = wid >> 2;
    const int px0 = pg << 5;
    const int b = blockIdx.x >> 5;
    const int p0 = (blockIdx.x & 31) << 7;

    const float* zb = z + (size_t)b * 128 * 4096 + p0;

    hh_s[tid] = g_hhalf[tid];
    if (tid < 128) bestS[tid] = ~0ull;

    // ---- Z producer: split z tile into tf32 hi/lo fragment planes ----
    {
        int px = tid & 127, kh = (tid >> 7) & 1, sel = tid >> 8;
        const float* zc = zb + px + (size_t)kh * 64 * 4096;
        float* Zh = SMF + (0 * 2 + kh) * 9216 + px * 72;
        float* Zl = SMF + (1 * 2 + kh) * 9216 + px * 72;
        int swz = 2 * ((px >> 2) & 3);
        #pragma unroll
        for (int Ti = 0; Ti < 4; ++Ti) {
            int T = sel * 4 + Ti;
            #pragma unroll
            for (int j = 0; j < 4; ++j) {
                float v0 = zc[(size_t)(8 * T + j) * 4096];
                float v1 = zc[(size_t)(8 * T + j + 4) * 4096];
                float h0, l0, h1, l1;
                tf32split(v0, h0, l0);
                tf32split(v1, h1, l1);
                int kp = (8 * T + 2 * j) ^ swz;
                *(float2*)(Zh + kp) = make_float2(h0, h1);
                *(float2*)(Zl + kp) = make_float2(l0, l1);
            }
        }
    }

    // ---- cp.async pipeline bases ----
    const u32 sb = smem_u32(SMF);
    const u32 ebA = sb + EOFF * 4, ebB = sb + (EOFF + 8192) * 4;

    // issue sub-chunk c (32KB) into buffer (c&1)
    auto issue = [&](int c) {
        const float* src = g_Eimg + (size_t)c * 8192;
        u32 dst = (c & 1) ? ebB : ebA;
        #pragma unroll
        for (int i = 0; i < 4; ++i)
            cp16(dst + (u32)(tid + i * 512) * 16, src + (size_t)(tid + i * 512) * 4);
        CP_COMMIT();
    };

    issue(0);

    const int s0 = 2 * (q >> 2);
    const int s1 = s0 + 4;
    const float* ebufA = SMF + EOFF;
    const float* ebufB = SMF + EOFF + 8192;

    for (int h = 0; h < 2; ++h) {
        float acc[2][8][4];
        #pragma unroll
        for (int m = 0; m < 2; ++m)
            #pragma unroll
            for (int n = 0; n < 8; ++n)
                #pragma unroll
                for (int r = 0; r < 4; ++r) acc[m][n][r] = 0.f;

        for (int ce = 0; ce < 4; ++ce) {
            int s = h * 8 + ce * 2;
            // --- Bh sub-chunk (buffer A): passes Ah*Bh + Al*Bh ---
            issue(s + 1);              // s+1 <= 15 always
            CP_WAIT1();
            __syncthreads();
            mma_block(SMF, ebufA, ce, px0, cg, q, lane, jj, s0, s1, true, acc);
            __syncthreads();
            // --- Bl sub-chunk (buffer B): pass Ah*Bl ---
            if (s + 2 < 16) { issue(s + 2); CP_WAIT1(); }
            else            { CP_WAIT0(); }
            __syncthreads();
            mma_block(SMF, ebufB, ce, px0, cg, q, lane, jj, s0, s1, false, acc);
            __syncthreads();
        }

        // ---- per-half argmin: dist = 0.5||e||^2 - z.e ----
        #pragma unroll
        for (int m = 0; m < 2; ++m) {
            ull bA = ~0ull, bB = ~0ull;
            #pragma unroll
            for (int n = 0; n < 8; ++n) {
                int c = h * 256 + cg * 64 + 8 * n + 2 * jj;
                float hc0 = hh_s[c], hc1 = hh_s[c + 1];
                ull kA0 = ((ull)fkey(hc0 - acc[m][n][0]) << 32) | (u32)c;
                ull kA1 = ((ull)fkey(hc1 - acc[m][n][1]) << 32) | (u32)(c + 1);
                ull kB0 = ((ull)fkey(hc0 - acc[m][n][2]) << 32) | (u32)c;
                ull kB1 = ((ull)fkey(hc1 - acc[m][n][3]) << 32) | (u32)(c + 1);
                ull a  = kA0 < kA1 ? kA0 : kA1;
                ull bb = kB0 < kB1 ? kB0 : kB1;
                if (a < bA) bA = a;
                if (bb < bB) bB = bb;
            }
            #pragma unroll
            for (int d = 1; d <= 2; d <<= 1) {
                ull oa = __shfl_xor_sync(0xffffffffu, bA, d);
                ull ob = __shfl_xor_sync(0xffffffffu, bB, d);
                if (oa < bA) bA = oa;
                if (ob < bB) bB = ob;
            }
            if (jj == 0) {
                atomicMin(&bestS[px0 + 16 * m + q], bA);
                atomicMin(&bestS[px0 + 16 * m + q + 8], bB);
            }
        }
    }

    __syncthreads();   // bestS final; Z planes reusable as gather staging

    // ---- gather winning rows into Qs[c][px], then coalesced write ----
    {
        int px = tid >> 2, qu = tid & 3;
        u32 idx = (u32)bestS[px];
        const float* er = emb + (size_t)idx * 128 + 32 * qu;
        float* Qs = SMF;
        #pragma unroll
        for (int i = 0; i < 8; ++i) {
            float4 v = *(const float4*)(er + 4 * i);
            int c = 32 * qu + 4 * i;
            Qs[(c + 0) * QS_STRIDE + px] = v.x;
            Qs[(c + 1) * QS_STRIDE + px] = v.y;
            Qs[(c + 2) * QS_STRIDE + px] = v.z;
            Qs[(c + 3) * QS_STRIDE + px] = v.w;
        }
    }
    __syncthreads();
    {
        int r = tid >> 2, qu = tid & 3;
        float* orow = out + (size_t)b * 128 * 4096 + (size_t)r * 4096 + p0 + 32 * qu;
        const float* qrow = SMF + r * QS_STRIDE + 32 * qu;
        #pragma unroll
        for (int i = 0; i < 8; ++i)
            *(float4*)(orow + 4 * i) = *(const float4*)(qrow + 4 * i);
    }
}

extern "C" void kernel_launch(void* const* d_in, const int* in_sizes, int n_in,
                              void* d_out, int out_size) {
    const float* z   = (const float*)d_in[0];   // (32,128,64,64) fp32
    const float* emb = (const float*)d_in[1];   // (512,128) fp32
    float* out = (float*)d_out;

    cudaFuncSetAttribute(vq_mma_kernel,
                         cudaFuncAttributeMaxDynamicSharedMemorySize, SMEM_BYTES);

    vq_prep<<<64, 256>>>(emb);
    vq_mma_kernel<<<1024, 512, SMEM_BYTES>>>(z, emb, out);
}

// round 6
// speedup vs baseline: 1.3896x; 1.0636x over previous
#include <cuda_runtime.h>
#include <cstdint>

typedef unsigned long long ull;
typedef unsigned int u32;

// ---------------- global scratch (static, no allocs) ----------------
// E fragment image: [h(2)][ce(4)][hl(2)][tl(4)][nblk(32)][64 floats] = 512KB
// granule g = h*16+ce*4+hl*2+tlp -> contiguous 4096 floats (16KB)
__device__ __align__(16) float g_Eimg[131072];
__device__ float g_hhalf[512];   // 0.5*||e_k||^2

__device__ __forceinline__ void tf32split(float v, float& hi, float& lo) {
    u32 uh; asm("cvt.rna.tf32.f32 %0, %1;" : "=r"(uh) : "f"(v));
    hi = __uint_as_float(uh);
    float r = v - hi;
    u32 ul; asm("cvt.rna.tf32.f32 %0, %1;" : "=r"(ul) : "f"(r));
    lo = __uint_as_float(ul);
}
__device__ __forceinline__ unsigned fkey(float f) {   // monotonic float->uint
    unsigned u = __float_as_uint(f);
    return (u & 0x80000000u) ? ~u : (u | 0x80000000u);
}
__device__ __forceinline__ void mma8(float* c, float2 a02, float2 a13, float2 b) {
    asm("mma.sync.aligned.m16n8k8.row.col.f32.tf32.tf32.f32 "
        "{%0,%1,%2,%3}, {%4,%5,%6,%7}, {%8,%9}, {%0,%1,%2,%3};"
        : "+f"(c[0]), "+f"(c[1]), "+f"(c[2]), "+f"(c[3])
        : "r"(__float_as_uint(a02.x)), "r"(__float_as_uint(a13.x)),
          "r"(__float_as_uint(a02.y)), "r"(__float_as_uint(a13.y)),
          "r"(__float_as_uint(b.x)),  "r"(__float_as_uint(b.y)));
}
__device__ __forceinline__ u32 smem_u32(const void* p) {
    u32 a;
    asm("{ .reg .u64 t; cvta.to.shared.u64 t, %1; cvt.u32.u64 %0, t; }" : "=r"(a) : "l"(p));
    return a;
}
__device__ __forceinline__ void cp16(u32 dst, const void* src) {
    asm volatile("cp.async.cg.shared.global [%0], [%1], 16;" :: "r"(dst), "l"(src));
}
#define CP_COMMIT() asm volatile("cp.async.commit_group;" ::: "memory")
#define CP_WAIT0()  asm volatile("cp.async.wait_group 0;" ::: "memory")

// ---------------- prep: build E fragment image + half-norms ----------------
__global__ void vq_prep(const float* __restrict__ emb) {
    int t = blockIdx.x * blockDim.x + threadIdx.x;
    int nt = gridDim.x * blockDim.x;
    for (int i = t; i < 512 * 128; i += nt) {
        int code = i >> 7, k = i & 127;
        int h = code >> 8, nblk = (code >> 3) & 31, colg = code & 7;
        int ce = k >> 5, tl = (k >> 3) & 3, j = k & 3, c = (k >> 2) & 1;
        int slot = 2 * (4 * colg + j) + c;
        float hi, lo;
        tf32split(emb[i], hi, lo);
        int base = (((h * 4 + ce) * 2 + 0) * 4 + tl) * 2048 + nblk * 64 + slot;
        g_Eimg[base] = hi;              // hl=0 plane
        g_Eimg[base + 8192] = lo;       // hl=1 plane
    }
    if (t < 512) {
        const float* row = emb + t * 128;
        float s = 0.f;
        #pragma unroll 4
        for (int c = 0; c < 128; ++c) { float v = row[c]; s += v * v; }
        g_hhalf[t] = 0.5f * s;
    }
}

// ---------------- main kernel ----------------
// SMEM float offsets (64-px CTA):
//  Z planes [(ahl*2+kh)]: 4 x 4608   -> 0 .. 18432  (px stride 72)
//  E buffers: 2 x 4096               -> 18432 .. 26624
//  hh[512]                           -> 26624
//  bestS[64] (ull)                   -> float idx 27136
#define ZPLANE 4608
#define EOFF   18432
#define HHOFF  26624
#define BESTF  27136
#define SMEM_BYTES ((BESTF + 128) * 4)
#define QS_STRIDE 68

__device__ __forceinline__ void mma_granule(
    const float* __restrict__ SMF, const float* __restrict__ ebuf,
    int ce, int tlp, int px0, int cg, int q, int lane, int jj, int s0, int s1,
    bool twoPass, float acc[2][8][4])
{
    #pragma unroll
    for (int tli = 0; tli < 2; ++tli) {
        int tl = tlp * 2 + tli;
        int t = ce * 4 + tl;
        const float* Zh = SMF + (t >> 3) * ZPLANE;
        const float* Zl = SMF + (2 + (t >> 3)) * ZPLANE;
        int koff = 8 * (t & 7) + 2 * jj;
        const float* Eb = ebuf + tli * 2048 + cg * 512 + 2 * lane;
        float2 Bf[8];
        #pragma unroll
        for (int n = 0; n < 8; ++n) Bf[n] = *(const float2*)(Eb + n * 64);
        float2 A00 = *(const float2*)(Zh + (px0 + q) * 72      + (koff ^ s0));
        float2 A01 = *(const float2*)(Zh + (px0 + q + 8) * 72  + (koff ^ s1));
        float2 A10 = *(const float2*)(Zh + (px0 + q + 16) * 72 + (koff ^ s0));
        float2 A11 = *(const float2*)(Zh + (px0 + q + 24) * 72 + (koff ^ s1));
        #pragma unroll
        for (int n = 0; n < 8; ++n) {
            mma8(acc[0][n], A00, A01, Bf[n]);
            mma8(acc[1][n], A10, A11, Bf[n]);
        }
        if (twoPass) {   // A-lo pass reusing same B fragments (Bh granule)
            A00 = *(const float2*)(Zl + (px0 + q) * 72      + (koff ^ s0));
            A01 = *(const float2*)(Zl + (px0 + q + 8) * 72  + (koff ^ s1));
            A10 = *(const float2*)(Zl + (px0 + q + 16) * 72 + (koff ^ s0));
            A11 = *(const float2*)(Zl + (px0 + q + 24) * 72 + (koff ^ s1));
            #pragma unroll
            for (int n = 0; n < 8; ++n) {
                mma8(acc[0][n], A00, A01, Bf[n]);
                mma8(acc[1][n], A10, A11, Bf[n]);
            }
        }
    }
}

__global__ __launch_bounds__(256, 2)
void vq_mma_kernel(const float* __restrict__ z, const float* __restrict__ emb,
                   float* __restrict__ out) {
    extern __shared__ float SMF[];
    float* hh_s = SMF + HHOFF;
    ull* bestS = (ull*)(SMF + BESTF);

    const int tid = threadIdx.x;
    const int wid = tid >> 5, lane = tid & 31;
    const int jj = lane & 3, q = lane >> 2;
    const int pg = wid & 1, cg = wid >> 1;          // 2 px-groups x 4 code-groups
    const int px0 = pg << 5;
    const int b = blockIdx.x >> 6;
    const int p0 = (blockIdx.x & 63) << 6;          // 64-px tile

    const float* zb = z + (size_t)b * 128 * 4096 + p0;

    hh_s[tid] = g_hhalf[tid];
    hh_s[tid + 256] = g_hhalf[tid + 256];
    if (tid < 64) bestS[tid] = ~0ull;

    // ---- Z producer: split 64px x 128k tile into tf32 hi/lo fragment planes ----
    {
        int px = tid & 63, kq = tid >> 6;           // kq: k quarter (32 k each)
        int kh = kq >> 1, kb = (kq & 1) * 32;       // plane half, local base
        const float* zc = zb + px + (size_t)(kq * 32) * 4096;
        float* Zh = SMF + (0 * 2 + kh) * ZPLANE + px * 72;
        float* Zl = SMF + (1 * 2 + kh) * ZPLANE + px * 72;
        int swz = 2 * ((px >> 2) & 3);
        #pragma unroll
        for (int T = 0; T < 4; ++T) {
            #pragma unroll
            for (int j = 0; j < 4; ++j) {
                float v0 = zc[(size_t)(8 * T + j) * 4096];
                float v1 = zc[(size_t)(8 * T + j + 4) * 4096];
                float h0, l0, h1, l1;
                tf32split(v0, h0, l0);
                tf32split(v1, h1, l1);
                int kp = (kb + 8 * T + 2 * j) ^ swz;
                *(float2*)(Zh + kp) = make_float2(h0, h1);
                *(float2*)(Zl + kp) = make_float2(l0, l1);
            }
        }
    }

    // ---- cp.async double-buffered E granule pipeline (16KB granules) ----
    const u32 sb = smem_u32(SMF);
    auto issue = [&](int g) {      // granule g (16KB) -> buffer g&1; 4 cp16/thread
        u32 dst = sb + (u32)(EOFF + (g & 1) * 4096) * 4;
        const float* src = g_Eimg + (size_t)g * 4096;
        #pragma unroll
        for (int i = 0; i < 4; ++i)
            cp16(dst + (u32)(tid + i * 256) * 16, src + (size_t)(tid + i * 256) * 4);
        CP_COMMIT();
    };
    issue(0);

    const int s0 = 2 * (q >> 2);
    const int s1 = s0 + 4;

    for (int h = 0; h < 2; ++h) {
        float acc[2][8][4];
        #pragma unroll
        for (int m = 0; m < 2; ++m)
            #pragma unroll
            for (int n = 0; n < 8; ++n)
                #pragma unroll
                for (int r = 0; r < 4; ++r) acc[m][n][r] = 0.f;

        for (int ce = 0; ce < 4; ++ce) {
            #pragma unroll
            for (int sub = 0; sub < 4; ++sub) {     // (hl,tlp): 00,01,10,11
                int g = h * 16 + ce * 4 + sub;
                CP_WAIT0();
                __syncthreads();                    // publish g; g-1 readers done
                if (g + 1 < 32) issue(g + 1);       // overlaps mma below
                mma_granule(SMF, SMF + EOFF + (g & 1) * 4096,
                            ce, sub & 1, px0, cg, q, lane, jj, s0, s1,
                            (sub >> 1) == 0, acc);
            }
        }

        // ---- per-half argmin: dist = 0.5||e||^2 - z.e ----
        #pragma unroll
        for (int m = 0; m < 2; ++m) {
            ull bA = ~0ull, bB = ~0ull;
            #pragma unroll
            for (int n = 0; n < 8; ++n) {
                int c = h * 256 + cg * 64 + 8 * n + 2 * jj;
                float hc0 = hh_s[c], hc1 = hh_s[c + 1];
                ull kA0 = ((ull)fkey(hc0 - acc[m][n][0]) << 32) | (u32)c;
                ull kA1 = ((ull)fkey(hc1 - acc[m][n][1]) << 32) | (u32)(c + 1);
                ull kB0 = ((ull)fkey(hc0 - acc[m][n][2]) << 32) | (u32)c;
                ull kB1 = ((ull)fkey(hc1 - acc[m][n][3]) << 32) | (u32)(c + 1);
                ull a  = kA0 < kA1 ? kA0 : kA1;
                ull bb = kB0 < kB1 ? kB0 : kB1;
                if (a < bA) bA = a;
                if (bb < bB) bB = bb;
            }
            #pragma unroll
            for (int d = 1; d <= 2; d <<= 1) {
                ull oa = __shfl_xor_sync(0xffffffffu, bA, d);
                ull ob = __shfl_xor_sync(0xffffffffu, bB, d);
                if (oa < bA) bA = oa;
                if (ob < bB) bB = ob;
            }
            if (jj == 0) {
                atomicMin(&bestS[px0 + 16 * m + q], bA);
                atomicMin(&bestS[px0 + 16 * m + q + 8], bB);
            }
        }
    }

    __syncthreads();   // bestS final; Z planes reusable as gather staging

    // ---- gather winning rows into Qs[c][px], then coalesced write ----
    {
        int px = tid >> 2, qu = tid & 3;
        u32 idx = (u32)bestS[px];
        const float* er = emb + (size_t)idx * 128 + 32 * qu;
        float* Qs = SMF;
        #pragma unroll
        for (int i = 0; i < 8; ++i) {
            float4 v = *(const float4*)(er + 4 * i);
            int c = 32 * qu + 4 * i;
            Qs[(c + 0) * QS_STRIDE + px] = v.x;
            Qs[(c + 1) * QS_STRIDE + px] = v.y;
            Qs[(c + 2) * QS_STRIDE + px] = v.z;
            Qs[(c + 3) * QS_STRIDE + px] = v.w;
        }
    }
    __syncthreads();
    {
        int r = tid >> 1, half = tid & 1;           // 128 rows x 2 halves of 32px
        float* orow = out + (size_t)b * 128 * 4096 + (size_t)r * 4096 + p0 + 32 * half;
        const float* qrow = SMF + r * QS_STRIDE + 32 * half;
        #pragma unroll
        for (int i = 0; i < 8; ++i)
            *(float4*)(orow + 4 * i) = *(const float4*)(qrow + 4 * i);
    }
}

extern "C" void kernel_launch(void* const* d_in, const int* in_sizes, int n_in,
                              void* d_out, int out_size) {
    const float* z   = (const float*)d_in[0];   // (32,128,64,64) fp32
    const float* emb = (const float*)d_in[1];   // (512,128) fp32
    float* out = (float*)d_out;

    cudaFuncSetAttribute(vq_mma_kernel,
                         cudaFuncAttributeMaxDynamicSharedMemorySize, SMEM_BYTES);

    vq_prep<<<64, 256>>>(emb);
    vq_mma_kernel<<<2048, 256, SMEM_BYTES>>>(z, emb, out);
}

// round 7
// speedup vs baseline: 2.0516x; 1.4763x over previous
#include <cuda_runtime.h>
#include <cuda_fp16.h>
#include <cstdint>

typedef unsigned long long ull;
typedef unsigned int u32;

// ---------------- global scratch (static, no allocs) ----------------
// E fragment image (fp16x2 u32 words): granule g = h*8+ks -> 4096 u32 (16KB)
//   granule layout: [hl(2)][nblk(32)][64 u32]; slot = 8*q + 2*jj + s
//   word (nblk,q,jj,s) = codes (h*256+nblk*8+q), kpair (ks*8 + jj + 4*s), fp16x2 (k even in lo)
__device__ __align__(16) u32 g_Eimg2[65536];     // 256KB
__device__ float g_hhalf[512];                   // 0.5*||e_k||^2

__device__ __forceinline__ u32 packsplit_hi(float v0, float v1, float& r0, float& r1) {
    __half h0 = __float2half_rn(v0), h1 = __float2half_rn(v1);
    r0 = v0 - __half2float(h0);
    r1 = v1 - __half2float(h1);
    return (u32)__half_as_ushort(h0) | ((u32)__half_as_ushort(h1) << 16);
}
__device__ __forceinline__ u32 pack_lo(float r0, float r1) {
    __half l0 = __float2half_rn(r0), l1 = __float2half_rn(r1);
    return (u32)__half_as_ushort(l0) | ((u32)__half_as_ushort(l1) << 16);
}
__device__ __forceinline__ unsigned fkey(float f) {   // monotonic float->uint
    unsigned u = __float_as_uint(f);
    return (u & 0x80000000u) ? ~u : (u | 0x80000000u);
}
__device__ __forceinline__ void mma16(float* c, u32 a0, u32 a1, u32 a2, u32 a3,
                                      u32 b0, u32 b1) {
    asm("mma.sync.aligned.m16n8k16.row.col.f32.f16.f16.f32 "
        "{%0,%1,%2,%3}, {%4,%5,%6,%7}, {%8,%9}, {%0,%1,%2,%3};"
        : "+f"(c[0]), "+f"(c[1]), "+f"(c[2]), "+f"(c[3])
        : "r"(a0), "r"(a1), "r"(a2), "r"(a3), "r"(b0), "r"(b1));
}
__device__ __forceinline__ u32 smem_u32(const void* p) {
    u32 a;
    asm("{ .reg .u64 t; cvta.to.shared.u64 t, %1; cvt.u32.u64 %0, t; }" : "=r"(a) : "l"(p));
    return a;
}
__device__ __forceinline__ void cp16(u32 dst, const void* src) {
    asm volatile("cp.async.cg.shared.global [%0], [%1], 16;" :: "r"(dst), "l"(src));
}
#define CP_COMMIT() asm volatile("cp.async.commit_group;" ::: "memory")
#define CP_WAIT0()  asm volatile("cp.async.wait_group 0;" ::: "memory")

// ---------------- prep: build fp16 split E image + half-norms ----------------
__global__ void vq_prep(const float* __restrict__ emb) {
    int t = blockIdx.x * blockDim.x + threadIdx.x;
    int nt = gridDim.x * blockDim.x;
    for (int i = t; i < 512 * 64; i += nt) {       // (code, kpair)
        int code = i >> 6, p = i & 63;
        float v0 = emb[code * 128 + 2 * p], v1 = emb[code * 128 + 2 * p + 1];
        float r0, r1;
        u32 hi = packsplit_hi(v0, v1, r0, r1);
        u32 lo = pack_lo(r0, r1);
        int h = code >> 8, c8 = code & 255;
        int nblk = c8 >> 3, q = c8 & 7;
        int ks = p >> 3, j = p & 7, jj = j & 3, s = j >> 2;
        int idx = (h * 8 + ks) * 4096 + nblk * 64 + 8 * q + 2 * jj + s;
        g_Eimg2[idx] = hi;             // hl=0
        g_Eimg2[idx + 2048] = lo;      // hl=1
    }
    if (t < 512) {
        const float* row = emb + t * 128;
        float s = 0.f;
        #pragma unroll 4
        for (int c = 0; c < 128; ++c) { float v = row[c]; s += v * v; }
        g_hhalf[t] = 0.5f * s;
    }
}

// ---------------- main kernel ----------------
// SMEM u32 offsets (64-px CTA):
//  ZH plane: 64 rows x 72 u32 -> 0 .. 4608
//  ZL plane:                  -> 4608 .. 9216
//  E buffers: 2 x 4096        -> 9216 .. 17408
//  hh[512] floats             -> 17408 .. 17920
//  bestS[64] ull              -> 17920 .. 18048
#define ZLOFF  4608
#define EOFF   9216
#define HHOFF  17408
#define BESTU  17920
#define SMEM_BYTES (18048 * 4 + 256)
#define QS_STRIDE 68

__global__ __launch_bounds__(256, 2)
void vq_mma_kernel(const float* __restrict__ z, const float* __restrict__ emb,
                   float* __restrict__ out) {
    extern __shared__ float SMF[];
    u32* ZU = (u32*)SMF;
    float* hh_s = SMF + HHOFF;
    ull* bestS = (ull*)(SMF + BESTU);

    const int tid = threadIdx.x;
    const int wid = tid >> 5, lane = tid & 31;
    const int jj = lane & 3, q = lane >> 2;
    const int pg = wid & 1, cg = wid >> 1;          // 2 px-groups x 4 code-groups
    const int px0 = pg << 5;
    const int b = blockIdx.x >> 6;
    const int p0 = (blockIdx.x & 63) << 6;          // 64-px tile

    const float* zb = z + (size_t)b * 128 * 4096 + p0;

    hh_s[tid] = g_hhalf[tid];
    hh_s[tid + 256] = g_hhalf[tid + 256];
    if (tid < 64) bestS[tid] = ~0ull;

    // ---- Z producer: fp16-split 64px x 128k into hi/lo planes ----
    {
        int px = tid & 63, kg = tid >> 6;           // kg: 16 kpairs each
        u32* Zh = ZU + px * 72;
        u32* Zl = ZU + ZLOFF + px * 72;
        #pragma unroll
        for (int pi = 0; pi < 16; ++pi) {
            int p = kg * 16 + pi;
            float v0 = zb[(size_t)(2 * p) * 4096 + px];
            float v1 = zb[(size_t)(2 * p + 1) * 4096 + px];
            float r0, r1;
            u32 hi = packsplit_hi(v0, v1, r0, r1);
            u32 lo = pack_lo(r0, r1);
            int ks = p >> 3, j = p & 7;
            int col = ks * 8 + 2 * (j & 3) + (j >> 2);
            Zh[col] = hi;
            Zl[col] = lo;
        }
    }

    // ---- cp.async double-buffered granule pipeline (16KB granules) ----
    const u32 sb = smem_u32(SMF);
    auto issue = [&](int g) {      // granule g (4096 u32) -> buffer g&1
        u32 dst = sb + (u32)(EOFF + (g & 1) * 4096) * 4;
        const u32* src = g_Eimg2 + (size_t)g * 4096;
        #pragma unroll
        for (int i = 0; i < 4; ++i)
            cp16(dst + (u32)(tid + i * 256) * 16, src + (size_t)(tid + i * 256) * 4);
        CP_COMMIT();
    };
    issue(0);

    const int r0 = (px0 + q) * 72, r1 = (px0 + q + 8) * 72;
    const int r2 = (px0 + q + 16) * 72, r3 = (px0 + q + 24) * 72;

    for (int h = 0; h < 2; ++h) {
        float acc[2][8][4];
        #pragma unroll
        for (int m = 0; m < 2; ++m)
            #pragma unroll
            for (int n = 0; n < 8; ++n)
                #pragma unroll
                for (int r = 0; r < 4; ++r) acc[m][n][r] = 0.f;

        for (int ks = 0; ks < 8; ++ks) {
            int g = h * 8 + ks;
            CP_WAIT0();
            __syncthreads();                        // publish g; g-1 readers done
            if (g + 1 < 16) issue(g + 1);           // overlaps mma below

            const int col = ks * 8 + 2 * jj;
            uint2 ah0 = *(const uint2*)(ZU + r0 + col);
            uint2 ah1 = *(const uint2*)(ZU + r1 + col);
            uint2 ah2 = *(const uint2*)(ZU + r2 + col);
            uint2 ah3 = *(const uint2*)(ZU + r3 + col);
            uint2 al0 = *(const uint2*)(ZU + ZLOFF + r0 + col);
            uint2 al1 = *(const uint2*)(ZU + ZLOFF + r1 + col);
            uint2 al2 = *(const uint2*)(ZU + ZLOFF + r2 + col);
            uint2 al3 = *(const uint2*)(ZU + ZLOFF + r3 + col);

            const u32* ebuf = ZU + EOFF + (g & 1) * 4096 + cg * 512 + 2 * lane;
            #pragma unroll
            for (int n = 0; n < 8; ++n) {
                uint2 bh = *(const uint2*)(ebuf + n * 64);
                uint2 bl = *(const uint2*)(ebuf + 2048 + n * 64);
                mma16(acc[0][n], ah0.x, ah1.x, ah0.y, ah1.y, bh.x, bh.y);
                mma16(acc[1][n], ah2.x, ah3.x, ah2.y, ah3.y, bh.x, bh.y);
                mma16(acc[0][n], al0.x, al1.x, al0.y, al1.y, bh.x, bh.y);
                mma16(acc[1][n], al2.x, al3.x, al2.y, al3.y, bh.x, bh.y);
                mma16(acc[0][n], ah0.x, ah1.x, ah0.y, ah1.y, bl.x, bl.y);
                mma16(acc[1][n], ah2.x, ah3.x, ah2.y, ah3.y, bl.x, bl.y);
            }
        }

        // ---- per-half argmin: dist = 0.5||e||^2 - z.e ----
        #pragma unroll
        for (int m = 0; m < 2; ++m) {
            ull bA = ~0ull, bB = ~0ull;
            #pragma unroll
            for (int n = 0; n < 8; ++n) {
                int c = h * 256 + cg * 64 + 8 * n + 2 * jj;
                float hc0 = hh_s[c], hc1 = hh_s[c + 1];
                ull kA0 = ((ull)fkey(hc0 - acc[m][n][0]) << 32) | (u32)c;
                ull kA1 = ((ull)fkey(hc1 - acc[m][n][1]) << 32) | (u32)(c + 1);
                ull kB0 = ((ull)fkey(hc0 - acc[m][n][2]) << 32) | (u32)c;
                ull kB1 = ((ull)fkey(hc1 - acc[m][n][3]) << 32) | (u32)(c + 1);
                ull a  = kA0 < kA1 ? kA0 : kA1;
                ull bb = kB0 < kB1 ? kB0 : kB1;
                if (a < bA) bA = a;
                if (bb < bB) bB = bb;
            }
            #pragma unroll
            for (int d = 1; d <= 2; d <<= 1) {
                ull oa = __shfl_xor_sync(0xffffffffu, bA, d);
                ull ob = __shfl_xor_sync(0xffffffffu, bB, d);
                if (oa < bA) bA = oa;
                if (ob < bB) bB = ob;
            }
            if (jj == 0) {
                atomicMin(&bestS[px0 + 16 * m + q], bA);
                atomicMin(&bestS[px0 + 16 * m + q + 8], bB);
            }
        }
    }

    __syncthreads();   // bestS final; Z/E regions reusable as gather staging

    // ---- gather winning rows into Qs[c][px], then coalesced write ----
    {
        int px = tid >> 2, qu = tid & 3;
        u32 idx = (u32)bestS[px];
        const float* er = emb + (size_t)idx * 128 + 32 * qu;
        float* Qs = SMF;
        #pragma unroll
        for (int i = 0; i < 8; ++i) {
            float4 v = *(const float4*)(er + 4 * i);
            int c = 32 * qu + 4 * i;
            Qs[(c + 0) * QS_STRIDE + px] = v.x;
            Qs[(c + 1) * QS_STRIDE + px] = v.y;
            Qs[(c + 2) * QS_STRIDE + px] = v.z;
            Qs[(c + 3) * QS_STRIDE + px] = v.w;
        }
    }
    __syncthreads();
    {
        int r = tid >> 1, half = tid & 1;           // 128 ch x 2 halves of 32px
        float* orow = out + (size_t)b * 128 * 4096 + (size_t)r * 4096 + p0 + 32 * half;
        const float* qrow = SMF + r * QS_STRIDE + 32 * half;
        #pragma unroll
        for (int i = 0; i < 8; ++i)
            *(float4*)(orow + 4 * i) = *(const float4*)(qrow + 4 * i);
    }
}

extern "C" void kernel_launch(void* const* d_in, const int* in_sizes, int n_in,
                              void* d_out, int out_size) {
    const float* z   = (const float*)d_in[0];   // (32,128,64,64) fp32
    const float* emb = (const float*)d_in[1];   // (512,128) fp32
    float* out = (float*)d_out;

    cudaFuncSetAttribute(vq_mma_kernel,
                         cudaFuncAttributeMaxDynamicSharedMemorySize, SMEM_BYTES);

    vq_prep<<<64, 256>>>(emb);
    vq_mma_kernel<<<2048, 256, SMEM_BYTES>>>(z, emb, out);
}